// round 15
// baseline (speedup 1.0000x reference)
#include <cuda_runtime.h>
#include <cuda_fp16.h>
#include <math.h>
#include <stdint.h>

// Problem constants
#define TT   256
#define BB   32
#define DD   512
#define HH   8
#define HDd  64
#define ETA  4
#define RR   4
#define FEAT 256
#define MM   (TT*BB)        // 8192
#define LDP  2688           // 5*512 + 96 p + 32 pad  (21*128)
#define WROWS 2560          // 5*H*HD
#define WSZ  (HH*HDd*DD)    // 262144
#define PSZ  (HH*ETA*DD)    // 16384
#define NCH  16
#define TCH  (TT/NCH)       // 16

// Scratch (device globals; allocation-free per harness rules)
__device__ __half g_x   [(size_t)MM * DD];
__device__ __half g_w5  [(size_t)LDP * DD];
__device__ __half g_wo  [(size_t)DD * DD];
__device__ float  g_proj[(size_t)MM * LDP];
__device__ __half g_attn[(size_t)MM * DD];
__device__ float  g_scan[(size_t)NCH * 256 * 29 * 64];  // per (c,bh,d): ks16|ss4|vs4|Dk4|Dv1
__device__ float  g_init[(size_t)NCH * 256 * 24 * 64];  // per (c,bh,d): ks16|ss4|vs4

__global__ void cvt1_kernel(__half* __restrict__ dst, const float* __restrict__ src, int n) {
    int i = blockIdx.x * 256 + threadIdx.x;
    if (i < n) dst[i] = __float2half_rn(src[i]);
}

#define NW_TOTAL (5*WSZ + 4*PSZ + WSZ)
__global__ void cvtw_kernel(__half* __restrict__ w5, __half* __restrict__ wo,
                            const float* __restrict__ q, const float* __restrict__ k,
                            const float* __restrict__ v, const float* __restrict__ b,
                            const float* __restrict__ g,
                            const float* __restrict__ p1, const float* __restrict__ p2,
                            const float* __restrict__ p3, const float* __restrict__ o)
{
    int i = blockIdx.x * 256 + threadIdx.x;
    if (i >= NW_TOTAL) return;
    if (i < 5 * WSZ) {
        int seg = i / WSZ, j = i - seg * WSZ;
        const float* s = (seg == 0) ? q : (seg == 1) ? k : (seg == 2) ? v : (seg == 3) ? b : g;
        w5[i] = __float2half_rn(s[j]);
    } else if (i < 5 * WSZ + 4 * PSZ) {
        int j = i - 5 * WSZ;
        int seg = j / PSZ, jj = j - seg * PSZ;
        float val = 0.f;
        if (seg == 0) val = p1[jj];
        else if (seg == 1) val = p2[jj];
        else if (seg == 2) val = p3[jj];
        w5[5 * WSZ + j] = __float2half_rn(val);
    } else {
        int j = i - 5 * WSZ - 4 * PSZ;
        wo[j] = __float2half_rn(o[j]);
    }
}

// ---------------------------------------------------------------------------
// FP16 tensor-core GEMM (fp32 accum) — R9/R13 config verbatim.
// ---------------------------------------------------------------------------
#define GBM 128
#define GBN 128
#define GBK 16
#define KPADH 24
#define STG 3

template <typename OutT>
__global__ __launch_bounds__(256) void mma_gemm(
    const __half* __restrict__ A, const __half* __restrict__ B,
    OutT* __restrict__ C, int M, int N, int K, int ldc, const float* __restrict__ bias)
{
    __shared__ __half As[STG][GBM * KPADH];
    __shared__ __half Bs[STG][GBN * KPADH];

    const int tid  = threadIdx.x;
    const int lane = tid & 31;
    const int wid  = tid >> 5;
    const int wm   = wid & 1;
    const int wn   = wid >> 1;
    const int m0   = blockIdx.y * GBM;
    const int n0   = blockIdx.x * GBN;

    const unsigned asbase = (unsigned)__cvta_generic_to_shared(&As[0][0]);
    const unsigned bsbase = (unsigned)__cvta_generic_to_shared(&Bs[0][0]);

    const int a_r  = lane & 15;
    const int a_ch = (lane >> 4) * 8;
    const int b_r  = lane & 7;
    const int b_ch = ((lane >> 3) & 1) * 8;

    float acc[4][4][4];
#pragma unroll
    for (int i = 0; i < 4; i++)
#pragma unroll
        for (int j = 0; j < 4; j++)
#pragma unroll
            for (int c = 0; c < 4; c++) acc[i][j][c] = 0.f;

    auto prefetch = [&](int it, int buf) {
        const int k0 = it * GBK;
        {
            int row = tid >> 1;
            int c   = tid & 1;
            unsigned da = asbase + (unsigned)((buf * GBM * KPADH + row * KPADH + c * 8) * 2);
            const __half* sa = A + (size_t)(m0 + row) * K + k0 + c * 8;
            asm volatile("cp.async.ca.shared.global [%0], [%1], 16;\n" :: "r"(da), "l"(sa));
        }
        {
            int row = tid >> 1;
            int c   = tid & 1;
            unsigned db = bsbase + (unsigned)((buf * GBN * KPADH + row * KPADH + c * 8) * 2);
            const __half* sb = B + (size_t)(n0 + row) * K + k0 + c * 8;
            asm volatile("cp.async.ca.shared.global [%0], [%1], 16;\n" :: "r"(db), "l"(sb));
        }
        asm volatile("cp.async.commit_group;\n");
    };

    const int NIT = K / GBK;
    prefetch(0, 0);
    if (NIT > 1) prefetch(1, 1);

    int buf = 0, pf = 2;
    for (int it = 0; it < NIT; ++it) {
        if (it + 1 < NIT) {
            asm volatile("cp.async.wait_group 1;\n");
        } else {
            asm volatile("cp.async.wait_group 0;\n");
        }
        __syncthreads();

        uint32_t bf[4][2];
#pragma unroll
        for (int nt = 0; nt < 4; nt++) {
            unsigned addr = bsbase + (unsigned)((buf * GBN * KPADH +
                            (wn * 32 + nt * 8 + b_r) * KPADH + b_ch) * 2);
            asm volatile("ldmatrix.sync.aligned.m8n8.x2.shared.b16 {%0,%1}, [%2];"
                : "=r"(bf[nt][0]), "=r"(bf[nt][1]) : "r"(addr));
        }
        uint32_t af[4][4];
#pragma unroll
        for (int mt = 0; mt < 4; mt++) {
            unsigned addr = asbase + (unsigned)((buf * GBM * KPADH +
                            (wm * 64 + mt * 16 + a_r) * KPADH + a_ch) * 2);
            asm volatile("ldmatrix.sync.aligned.m8n8.x4.shared.b16 {%0,%1,%2,%3}, [%4];"
                : "=r"(af[mt][0]), "=r"(af[mt][1]), "=r"(af[mt][2]), "=r"(af[mt][3])
                : "r"(addr));
        }
#pragma unroll
        for (int mt = 0; mt < 4; mt++)
#pragma unroll
            for (int nt = 0; nt < 4; nt++) {
                asm volatile(
                    "mma.sync.aligned.m16n8k16.row.col.f32.f16.f16.f32 "
                    "{%0,%1,%2,%3}, {%4,%5,%6,%7}, {%8,%9}, {%0,%1,%2,%3};"
                    : "+f"(acc[mt][nt][0]), "+f"(acc[mt][nt][1]),
                      "+f"(acc[mt][nt][2]), "+f"(acc[mt][nt][3])
                    : "r"(af[mt][0]), "r"(af[mt][1]), "r"(af[mt][2]), "r"(af[mt][3]),
                      "r"(bf[nt][0]), "r"(bf[nt][1]));
            }

        if (it + 2 < NIT) prefetch(it + 2, pf);
        buf = (buf + 1 == STG) ? 0 : buf + 1;
        pf  = (pf  + 1 == STG) ? 0 : pf + 1;
    }

#pragma unroll
    for (int mt = 0; mt < 4; mt++) {
        int row = m0 + wm * 64 + mt * 16 + (lane >> 2);
#pragma unroll
        for (int nt = 0; nt < 4; nt++) {
            int col = n0 + wn * 32 + nt * 8 + (lane & 3) * 2;
            float b0v = bias ? bias[col]     : 0.f;
            float b1v = bias ? bias[col + 1] : 0.f;
            float a0 = acc[mt][nt][0] + b0v, a1 = acc[mt][nt][1] + b1v;
            float a2 = acc[mt][nt][2] + b0v, a3 = acc[mt][nt][3] + b1v;
            if constexpr (sizeof(OutT) == 2) {
                *reinterpret_cast<__half2*>(&C[(size_t)row * ldc + col]) =
                    __floats2half2_rn(a0, a1);
                *reinterpret_cast<__half2*>(&C[(size_t)(row + 8) * ldc + col]) =
                    __floats2half2_rn(a2, a3);
            } else {
                *reinterpret_cast<float2*>(&C[(size_t)row * ldc + col]) = make_float2(a0, a1);
                *reinterpret_cast<float2*>(&C[(size_t)(row + 8) * ldc + col]) = make_float2(a2, a3);
            }
        }
    }
}

// ---------------------------------------------------------------------------
// Recurrence — chunked parallel scan (NCH=16).
// ---------------------------------------------------------------------------
__device__ __forceinline__ float sigf(float x) {
    return 1.f / (1.f + __expf(-x));
}

#define NBUF 4

// Full staging (q,k,v,b,g + p + term) — used in pass 3.
#define STAGE_BODY(T_, BUF_)                                                          \
    do {                                                                              \
        const int m_ = (T_) * BB + b;                                                 \
        {                                                                             \
            const int seg_ = d >> 4;                                                  \
            const int j_ = (d & 15) * 4;                                              \
            const float* src_ = proj + (size_t)m_ * LDP + seg_ * 512 + h * HDd + j_;  \
            unsigned dst_ = (unsigned)__cvta_generic_to_shared(&sstage[BUF_][seg_][j_]); \
            asm volatile("cp.async.ca.shared.global [%0], [%1], 16;\n" :: "r"(dst_), "l"(src_)); \
        }                                                                             \
        if (d < 16) {                                                                 \
            const float* src_ = proj + (size_t)m_ * LDP + 4 * 512 + h * HDd + d * 4;  \
            unsigned dst_ = (unsigned)__cvta_generic_to_shared(&sstage[BUF_][4][d * 4]); \
            asm volatile("cp.async.ca.shared.global [%0], [%1], 16;\n" :: "r"(dst_), "l"(src_)); \
        } else if (d < 19) {                                                          \
            const int j_ = d - 16;                                                    \
            const float* src_ = proj + (size_t)m_ * LDP + WROWS + j_ * 32 + h * ETA;  \
            unsigned dst_ = (unsigned)__cvta_generic_to_shared(&sp[BUF_][j_][0]);     \
            asm volatile("cp.async.ca.shared.global [%0], [%1], 16;\n" :: "r"(dst_), "l"(src_)); \
        } else if (d == 19) {                                                         \
            const int* src_ = term + m_;                                              \
            unsigned dst_ = (unsigned)__cvta_generic_to_shared(&sterm[BUF_]);         \
            asm volatile("cp.async.ca.shared.global [%0], [%1], 4;\n" :: "r"(dst_), "l"(src_)); \
        }                                                                             \
        asm volatile("cp.async.commit_group;\n");                                     \
    } while (0)

// q-free staging (segs 1-4 via all 64 threads) — used in pass 1.
#define STAGE_BODY_NOQ(T_, BUF_)                                                      \
    do {                                                                              \
        const int m_ = (T_) * BB + b;                                                 \
        {                                                                             \
            const int seg_ = 1 + (d >> 4);                                            \
            const int j_ = (d & 15) * 4;                                              \
            const float* src_ = proj + (size_t)m_ * LDP + seg_ * 512 + h * HDd + j_;  \
            unsigned dst_ = (unsigned)__cvta_generic_to_shared(&sstage[BUF_][seg_][j_]); \
            asm volatile("cp.async.ca.shared.global [%0], [%1], 16;\n" :: "r"(dst_), "l"(src_)); \
        }                                                                             \
        if (d < 3) {                                                                  \
            const float* src_ = proj + (size_t)m_ * LDP + WROWS + d * 32 + h * ETA;   \
            unsigned dst_ = (unsigned)__cvta_generic_to_shared(&sp[BUF_][d][0]);      \
            asm volatile("cp.async.ca.shared.global [%0], [%1], 16;\n" :: "r"(dst_), "l"(src_)); \
        } else if (d == 3) {                                                          \
            const int* src_ = term + m_;                                              \
            unsigned dst_ = (unsigned)__cvta_generic_to_shared(&sterm[BUF_]);         \
            asm volatile("cp.async.ca.shared.global [%0], [%1], 4;\n" :: "r"(dst_), "l"(src_)); \
        }                                                                             \
        asm volatile("cp.async.commit_group;\n");                                     \
    } while (0)

#define OSC_INIT(BASE_)                                                   \
    const float PI = 3.14159265358979323846f;                             \
    float cr0, cr1, cr2, cr3, sr0, sr1, sr2, sr3;                         \
    float cw0, cw1, cw2, cw3, sw0, sw1, sw2, sw3;                         \
    {                                                                     \
        float om0 = -PI;                                                  \
        float om1 = -PI + 2.f * PI / 3.f;                                 \
        float om2 = -PI + 4.f * PI / 3.f;                                 \
        float om3 = PI;                                                   \
        float a;                                                          \
        a = (BASE_) * om0; cr0 = cosf(a); sr0 = sinf(a);                  \
        a = (BASE_) * om1; cr1 = cosf(a); sr1 = sinf(a);                  \
        a = (BASE_) * om2; cr2 = cosf(a); sr2 = sinf(a);                  \
        a = (BASE_) * om3; cr3 = cosf(a); sr3 = sinf(a);                  \
        cw0 = cosf(om0); sw0 = sinf(om0);                                 \
        cw1 = cosf(om1); sw1 = sinf(om1);                                 \
        cw2 = cosf(om2); sw2 = sinf(om2);                                 \
        cw3 = cosf(om3); sw3 = sinf(om3);                                 \
    }

#define OSC_STEP()                                                        \
    do { float c2_, s2_;                                                  \
        c2_ = cr0 * cw0 - sr0 * sw0; s2_ = sr0 * cw0 + cr0 * sw0; cr0 = c2_; sr0 = s2_; \
        c2_ = cr1 * cw1 - sr1 * sw1; s2_ = sr1 * cw1 + cr1 * sw1; cr1 = c2_; sr1 = s2_; \
        c2_ = cr2 * cw2 - sr2 * sw2; s2_ = sr2 * cw2 + cr2 * sw2; cr2 = c2_; sr2 = s2_; \
        c2_ = cr3 * cw3 - sr3 * sw3; s2_ = sr3 * cw3 + cr3 * sw3; cr3 = c2_; sr3 = s2_; \
    } while (0)

// Pass 1: chunk-local scan from zero state (no q needed).
__global__ __launch_bounds__(64) void scan_local(
    const float* __restrict__ proj, const int* __restrict__ term,
    const float* __restrict__ tick, float* __restrict__ scan)
{
    const int bh = blockIdx.x;
    const int c  = blockIdx.y;
    const int b = bh >> 3;
    const int h = bh & 7;
    const int d = threadIdx.x;
    const int t0 = c * TCH;

    __shared__ __align__(16) float sstage[NBUF][5][64];
    __shared__ __align__(16) float sp[NBUF][3][4];
    __shared__ int sterm[NBUF];

    float ks[4][4] = {}, ss[4] = {}, vs[4] = {};
    float Dk[4] = {1.f, 1.f, 1.f, 1.f}, Dv = 1.f;

    const float tk = tick[b];
    OSC_INIT((float)t0 + 1.f + tk);

    STAGE_BODY_NOQ(t0 + 0, 0);
    STAGE_BODY_NOQ(t0 + 1, 1);
    STAGE_BODY_NOQ(t0 + 2, 2);
    asm volatile("cp.async.wait_group 2;\n");
    __syncthreads();

    for (int tt = 0; tt < TCH; tt++) {
        const int buf = tt & (NBUF - 1);

        const float kd = sstage[buf][1][d];
        const float vv = sstage[buf][2][d];
        const float bd = sigf(sstage[buf][3][d]);
        const float gd = sigf(sstage[buf][4][d]);
        const float tf = 1.f - (float)sterm[buf];

#pragma unroll
        for (int e = 0; e < 4; e++) {
            const float psi = fmaxf(kd * sp[buf][0][e], 0.f);
            const float gf  = gd * sigf(sp[buf][2][e]);
            const float gk  = psi * gf;
            const float dg  = (1.f - gf) * tf;
            ss[e] = dg * ss[e] + gk;
            ks[e][0] = dg * ks[e][0] + gk * cr0;
            ks[e][1] = dg * ks[e][1] + gk * cr1;
            ks[e][2] = dg * ks[e][2] + gk * cr2;
            ks[e][3] = dg * ks[e][3] + gk * cr3;
            Dk[e] *= dg;
        }
        const float bv = vv * bd;
        const float om = (1.f - bd) * tf;
        vs[0] = om * vs[0] + bv * cr0;
        vs[1] = om * vs[1] + bv * cr1;
        vs[2] = om * vs[2] + bv * cr2;
        vs[3] = om * vs[3] + bv * cr3;
        Dv *= om;

        if (tt + 3 < TCH) {
            STAGE_BODY_NOQ(t0 + tt + 3, (tt + 3) & (NBUF - 1));
            asm volatile("cp.async.wait_group 2;\n");
        } else if (tt + 2 < TCH) {
            asm volatile("cp.async.wait_group 1;\n");
        } else {
            asm volatile("cp.async.wait_group 0;\n");
        }
        __syncthreads();
        OSC_STEP();
    }

    float* out = scan + (((size_t)c * 256 + bh) * 29) * 64;
#pragma unroll
    for (int e = 0; e < 4; e++)
#pragma unroll
        for (int r = 0; r < 4; r++)
            out[(e * 4 + r) * 64 + d] = ks[e][r];
#pragma unroll
    for (int e = 0; e < 4; e++) out[(16 + e) * 64 + d] = ss[e];
#pragma unroll
    for (int r = 0; r < 4; r++) out[(20 + r) * 64 + d] = vs[r];
#pragma unroll
    for (int e = 0; e < 4; e++) out[(24 + e) * 64 + d] = Dk[e];
    out[28 * 64 + d] = Dv;
}

// Pass 2: sequential combine; writes each chunk's true initial state.
__global__ __launch_bounds__(64) void scan_combine(
    const float* __restrict__ scan,
    const float* __restrict__ tkp, const float* __restrict__ tvp,
    const float* __restrict__ sprev, float* __restrict__ init)
{
    const int bh = blockIdx.x;
    const int b = bh >> 3;
    const int h = bh & 7;
    const int d = threadIdx.x;

    float ks[4][4], ss[4], vs[4];
#pragma unroll
    for (int e = 0; e < 4; e++) {
#pragma unroll
        for (int r = 0; r < 4; r++)
            ks[e][r] = tkp[((size_t)(b * RR + r) * HH + h) * FEAT + e * 64 + d];
        ss[e] = sprev[((size_t)(b * HH + h)) * FEAT + e * 64 + d];
    }
#pragma unroll
    for (int r = 0; r < 4; r++)
        vs[r] = tvp[((size_t)(b * RR + r) * HH + h) * HDd + d];

    for (int c = 0; c < NCH; c++) {
        float* ini = init + (((size_t)c * 256 + bh) * 24) * 64;
#pragma unroll
        for (int e = 0; e < 4; e++)
#pragma unroll
            for (int r = 0; r < 4; r++)
                ini[(e * 4 + r) * 64 + d] = ks[e][r];
#pragma unroll
        for (int e = 0; e < 4; e++) ini[(16 + e) * 64 + d] = ss[e];
#pragma unroll
        for (int r = 0; r < 4; r++) ini[(20 + r) * 64 + d] = vs[r];

        const float* sc = scan + (((size_t)c * 256 + bh) * 29) * 64;
        float Dk[4], Dv;
#pragma unroll
        for (int e = 0; e < 4; e++) Dk[e] = sc[(24 + e) * 64 + d];
        Dv = sc[28 * 64 + d];
#pragma unroll
        for (int e = 0; e < 4; e++) {
#pragma unroll
            for (int r = 0; r < 4; r++)
                ks[e][r] = sc[(e * 4 + r) * 64 + d] + Dk[e] * ks[e][r];
            ss[e] = sc[(16 + e) * 64 + d] + Dk[e] * ss[e];
        }
#pragma unroll
        for (int r = 0; r < 4; r++)
            vs[r] = sc[(20 + r) * 64 + d] + Dv * vs[r];
    }
}

// Pass 3: per-chunk full recurrence with true initial state; emits attn.
__global__ __launch_bounds__(64) void scan_apply(
    const float* __restrict__ proj, const int* __restrict__ term,
    const float* __restrict__ tick, const float* __restrict__ init,
    __half* __restrict__ attn)
{
    const int bh = blockIdx.x;
    const int c  = blockIdx.y;
    const int b = bh >> 3;
    const int h = bh & 7;
    const int d = threadIdx.x;
    const int t0 = c * TCH;

    __shared__ __align__(16) float sstage[NBUF][5][64];
    __shared__ __align__(16) float sp[NBUF][3][4];
    __shared__ int sterm[NBUF];
    __shared__ float red[2][5][2];

    float ks[4][4], ss[4], vs[4];
    const float* ini = init + (((size_t)c * 256 + bh) * 24) * 64;
#pragma unroll
    for (int e = 0; e < 4; e++)
#pragma unroll
        for (int r = 0; r < 4; r++)
            ks[e][r] = ini[(e * 4 + r) * 64 + d];
#pragma unroll
    for (int e = 0; e < 4; e++) ss[e] = ini[(16 + e) * 64 + d];
#pragma unroll
    for (int r = 0; r < 4; r++) vs[r] = ini[(20 + r) * 64 + d];

    const float tk = tick[b];
    OSC_INIT((float)t0 + 1.f + tk);

    STAGE_BODY(t0 + 0, 0);
    STAGE_BODY(t0 + 1, 1);
    STAGE_BODY(t0 + 2, 2);
    asm volatile("cp.async.wait_group 2;\n");
    __syncthreads();

    const int warp = d >> 5;

    for (int tt = 0; tt < TCH; tt++) {
        const int buf = tt & (NBUF - 1);

        const float qd = sstage[buf][0][d];
        const float kd = sstage[buf][1][d];
        const float vv = sstage[buf][2][d];
        const float bd = sigf(sstage[buf][3][d]);
        const float gd = sigf(sstage[buf][4][d]);
        const float tf = 1.f - (float)sterm[buf];

        float v0 = 0.f, v1 = 0.f, v2 = 0.f, v3 = 0.f, v4 = 0.f;
#pragma unroll
        for (int e = 0; e < 4; e++) {
            const float phi = fmaxf(qd * sp[buf][1][e], 0.f);
            const float psi = fmaxf(kd * sp[buf][0][e], 0.f);
            const float gf  = gd * sigf(sp[buf][2][e]);
            const float gk  = psi * gf;
            const float dg  = (1.f - gf) * tf;

            ss[e] = dg * ss[e] + gk;
            v4 += ss[e] * phi;

            ks[e][0] = dg * ks[e][0] + gk * cr0;  v0 += ks[e][0] * phi;
            ks[e][1] = dg * ks[e][1] + gk * cr1;  v1 += ks[e][1] * phi;
            ks[e][2] = dg * ks[e][2] + gk * cr2;  v2 += ks[e][2] * phi;
            ks[e][3] = dg * ks[e][3] + gk * cr3;  v3 += ks[e][3] * phi;
        }

        const float bv = vv * bd;
        const float om = (1.f - bd) * tf;
        vs[0] = om * vs[0] + bv * cr0;
        vs[1] = om * vs[1] + bv * cr1;
        vs[2] = om * vs[2] + bv * cr2;
        vs[3] = om * vs[3] + bv * cr3;

#pragma unroll
        for (int o = 16; o > 0; o >>= 1) {
            v0 += __shfl_xor_sync(0xffffffffu, v0, o);
            v1 += __shfl_xor_sync(0xffffffffu, v1, o);
            v2 += __shfl_xor_sync(0xffffffffu, v2, o);
            v3 += __shfl_xor_sync(0xffffffffu, v3, o);
            v4 += __shfl_xor_sync(0xffffffffu, v4, o);
        }
        const int pb = tt & 1;
        if ((d & 31) == 0) {
            red[pb][0][warp] = v0;
            red[pb][1][warp] = v1;
            red[pb][2][warp] = v2;
            red[pb][3][warp] = v3;
            red[pb][4][warp] = v4;
        }

        if (tt + 3 < TCH) {
            STAGE_BODY(t0 + tt + 3, (tt + 3) & (NBUF - 1));
            asm volatile("cp.async.wait_group 2;\n");
        } else if (tt + 2 < TCH) {
            asm volatile("cp.async.wait_group 1;\n");
        } else {
            asm volatile("cp.async.wait_group 0;\n");
        }
        __syncthreads();

        const float kdq0 = red[pb][0][0] + red[pb][0][1];
        const float kdq1 = red[pb][1][0] + red[pb][1][1];
        const float kdq2 = red[pb][2][0] + red[pb][2][1];
        const float kdq3 = red[pb][3][0] + red[pb][3][1];
        const float norm = red[pb][4][0] + red[pb][4][1];

        const float kv = vs[0] * kdq0 + vs[1] * kdq1 + vs[2] * kdq2 + vs[3] * kdq3;
        const int m = (t0 + tt) * BB + b;
        attn[(size_t)m * DD + h * HDd + d] = __float2half_rn(kv / (8.f * norm + 1e-6f));

        OSC_STEP();
    }
}

// ---------------------------------------------------------------------------
extern "C" void kernel_launch(void* const* d_in, const int* in_sizes, int n_in,
                              void* d_out, int out_size)
{
    const float* inputs = (const float*)d_in[0];
    const int*   term   = (const int*)d_in[1];
    const float* tkp    = (const float*)d_in[2];
    const float* tvp    = (const float*)d_in[3];
    const float* sprev  = (const float*)d_in[4];
    const float* tick   = (const float*)d_in[5];
    const float* Wq     = (const float*)d_in[6];
    const float* Wk     = (const float*)d_in[7];
    const float* Wv     = (const float*)d_in[8];
    const float* Wb     = (const float*)d_in[9];
    const float* Wg     = (const float*)d_in[10];
    const float* Wp1    = (const float*)d_in[11];
    const float* Wp2    = (const float*)d_in[12];
    const float* Wp3    = (const float*)d_in[13];
    const float* Wo     = (const float*)d_in[14];
    const float* bo     = (const float*)d_in[15];

    void* p;
    cudaGetSymbolAddress(&p, g_x);    __half* x    = (__half*)p;
    cudaGetSymbolAddress(&p, g_w5);   __half* w5   = (__half*)p;
    cudaGetSymbolAddress(&p, g_wo);   __half* wo   = (__half*)p;
    cudaGetSymbolAddress(&p, g_proj); float*  proj = (float*)p;
    cudaGetSymbolAddress(&p, g_attn); __half* attn = (__half*)p;
    cudaGetSymbolAddress(&p, g_scan); float*  scan = (float*)p;
    cudaGetSymbolAddress(&p, g_init); float*  init = (float*)p;

    // Prologue conversions
    cvt1_kernel<<<(MM * DD + 255) / 256, 256>>>(x, inputs, MM * DD);
    cvtw_kernel<<<(NW_TOTAL + 255) / 256, 256>>>(w5, wo, Wq, Wk, Wv, Wb, Wg,
                                                 Wp1, Wp2, Wp3, Wo);

    // 1) Fused projection: (8192 x 2688), fp32 out
    {
        dim3 grid(LDP / GBN, MM / GBM);   // (21, 64)
        mma_gemm<float><<<grid, 256>>>(x, w5, proj, MM, LDP, DD, LDP, nullptr);
    }
    // 2) Recurrence as 3-pass parallel scan (16 chunks of 16 steps)
    {
        dim3 g1(BB * HH, NCH);
        scan_local<<<g1, 64>>>(proj, term, tick, scan);
        scan_combine<<<BB * HH, 64>>>(scan, tkp, tvp, sprev, init);
        scan_apply<<<g1, 64>>>(proj, term, tick, init, attn);
    }
    // 3) Output projection: out = attn @ Wo^T + bo  (8192 x 512), fp32 out
    {
        dim3 grid(DD / GBN, MM / GBM);    // (4, 64)
        mma_gemm<float><<<grid, 256>>>(attn, wo, (float*)d_out, MM, DD, DD, DD, bo);
    }
}

// round 16
// speedup vs baseline: 1.1022x; 1.1022x over previous
#include <cuda_runtime.h>
#include <cuda_fp16.h>
#include <math.h>
#include <stdint.h>

// Problem constants
#define TT   256
#define BB   32
#define DD   512
#define HH   8
#define HDd  64
#define ETA  4
#define RR   4
#define FEAT 256
#define MM   (TT*BB)        // 8192
#define LDP  2688           // 5*512 + 96 p + 32 pad  (21*128)
#define WROWS 2560          // 5*H*HD
#define WSZ  (HH*HDd*DD)    // 262144
#define PSZ  (HH*ETA*DD)    // 16384
#define NCH  8
#define TCH  (TT/NCH)       // 32

// Scratch (device globals; allocation-free per harness rules)
__device__ __half g_x   [(size_t)MM * DD];
__device__ __half g_w5  [(size_t)LDP * DD];
__device__ __half g_wo  [(size_t)DD * DD];
__device__ float  g_proj[(size_t)MM * LDP];
__device__ __half g_attn[(size_t)MM * DD];
__device__ float  g_scan[(size_t)NCH * 256 * 29 * 64];
__device__ float  g_init[(size_t)NCH * 256 * 24 * 64];

__device__ __forceinline__ float sigf(float x) {
    return 1.f / (1.f + __expf(-x));
}

__global__ void cvt1_kernel(__half* __restrict__ dst, const float* __restrict__ src, int n) {
    int i = blockIdx.x * 256 + threadIdx.x;
    if (i < n) dst[i] = __float2half_rn(src[i]);
}

#define NW_TOTAL (5*WSZ + 4*PSZ + WSZ)
__global__ void cvtw_kernel(__half* __restrict__ w5, __half* __restrict__ wo,
                            const float* __restrict__ q, const float* __restrict__ k,
                            const float* __restrict__ v, const float* __restrict__ b,
                            const float* __restrict__ g,
                            const float* __restrict__ p1, const float* __restrict__ p2,
                            const float* __restrict__ p3, const float* __restrict__ o)
{
    int i = blockIdx.x * 256 + threadIdx.x;
    if (i >= NW_TOTAL) return;
    if (i < 5 * WSZ) {
        int seg = i / WSZ, j = i - seg * WSZ;
        const float* s = (seg == 0) ? q : (seg == 1) ? k : (seg == 2) ? v : (seg == 3) ? b : g;
        w5[i] = __float2half_rn(s[j]);
    } else if (i < 5 * WSZ + 4 * PSZ) {
        int j = i - 5 * WSZ;
        int seg = j / PSZ, jj = j - seg * PSZ;
        float val = 0.f;
        if (seg == 0) val = p1[jj];
        else if (seg == 1) val = p2[jj];
        else if (seg == 2) val = p3[jj];
        w5[5 * WSZ + j] = __float2half_rn(val);
    } else {
        int j = i - 5 * WSZ - 4 * PSZ;
        wo[j] = __float2half_rn(o[j]);
    }
}

// ---------------------------------------------------------------------------
// FP16 tensor-core GEMM (fp32 accum): C = A @ B^T (+bias).
// sigmode=1: apply sigmoid to output columns [1536,2560) and [2624,2656)
// (beta/gamma and p3 segments of the fused projection).
// ---------------------------------------------------------------------------
#define GBM 128
#define GBN 128
#define GBK 16
#define KPADH 24
#define STG 3

__device__ __forceinline__ float maybe_sig(float v, int col, int sigmode) {
    if (sigmode && ((col >= 1536 && col < 2560) || (col >= 2624 && col < 2656)))
        return sigf(v);
    return v;
}

template <typename OutT>
__global__ __launch_bounds__(256) void mma_gemm(
    const __half* __restrict__ A, const __half* __restrict__ B,
    OutT* __restrict__ C, int M, int N, int K, int ldc,
    const float* __restrict__ bias, int sigmode)
{
    __shared__ __half As[STG][GBM * KPADH];
    __shared__ __half Bs[STG][GBN * KPADH];

    const int tid  = threadIdx.x;
    const int lane = tid & 31;
    const int wid  = tid >> 5;
    const int wm   = wid & 1;
    const int wn   = wid >> 1;
    const int m0   = blockIdx.y * GBM;
    const int n0   = blockIdx.x * GBN;

    const unsigned asbase = (unsigned)__cvta_generic_to_shared(&As[0][0]);
    const unsigned bsbase = (unsigned)__cvta_generic_to_shared(&Bs[0][0]);

    const int a_r  = lane & 15;
    const int a_ch = (lane >> 4) * 8;
    const int b_r  = lane & 7;
    const int b_ch = ((lane >> 3) & 1) * 8;

    float acc[4][4][4];
#pragma unroll
    for (int i = 0; i < 4; i++)
#pragma unroll
        for (int j = 0; j < 4; j++)
#pragma unroll
            for (int c = 0; c < 4; c++) acc[i][j][c] = 0.f;

    auto prefetch = [&](int it, int buf) {
        const int k0 = it * GBK;
        {
            int row = tid >> 1;
            int c   = tid & 1;
            unsigned da = asbase + (unsigned)((buf * GBM * KPADH + row * KPADH + c * 8) * 2);
            const __half* sa = A + (size_t)(m0 + row) * K + k0 + c * 8;
            asm volatile("cp.async.ca.shared.global [%0], [%1], 16;\n" :: "r"(da), "l"(sa));
        }
        {
            int row = tid >> 1;
            int c   = tid & 1;
            unsigned db = bsbase + (unsigned)((buf * GBN * KPADH + row * KPADH + c * 8) * 2);
            const __half* sb = B + (size_t)(n0 + row) * K + k0 + c * 8;
            asm volatile("cp.async.ca.shared.global [%0], [%1], 16;\n" :: "r"(db), "l"(sb));
        }
        asm volatile("cp.async.commit_group;\n");
    };

    const int NIT = K / GBK;
    prefetch(0, 0);
    if (NIT > 1) prefetch(1, 1);

    int buf = 0, pf = 2;
    for (int it = 0; it < NIT; ++it) {
        if (it + 1 < NIT) {
            asm volatile("cp.async.wait_group 1;\n");
        } else {
            asm volatile("cp.async.wait_group 0;\n");
        }
        __syncthreads();

        uint32_t bf[4][2];
#pragma unroll
        for (int nt = 0; nt < 4; nt++) {
            unsigned addr = bsbase + (unsigned)((buf * GBN * KPADH +
                            (wn * 32 + nt * 8 + b_r) * KPADH + b_ch) * 2);
            asm volatile("ldmatrix.sync.aligned.m8n8.x2.shared.b16 {%0,%1}, [%2];"
                : "=r"(bf[nt][0]), "=r"(bf[nt][1]) : "r"(addr));
        }
        uint32_t af[4][4];
#pragma unroll
        for (int mt = 0; mt < 4; mt++) {
            unsigned addr = asbase + (unsigned)((buf * GBM * KPADH +
                            (wm * 64 + mt * 16 + a_r) * KPADH + a_ch) * 2);
            asm volatile("ldmatrix.sync.aligned.m8n8.x4.shared.b16 {%0,%1,%2,%3}, [%4];"
                : "=r"(af[mt][0]), "=r"(af[mt][1]), "=r"(af[mt][2]), "=r"(af[mt][3])
                : "r"(addr));
        }
#pragma unroll
        for (int mt = 0; mt < 4; mt++)
#pragma unroll
            for (int nt = 0; nt < 4; nt++) {
                asm volatile(
                    "mma.sync.aligned.m16n8k16.row.col.f32.f16.f16.f32 "
                    "{%0,%1,%2,%3}, {%4,%5,%6,%7}, {%8,%9}, {%0,%1,%2,%3};"
                    : "+f"(acc[mt][nt][0]), "+f"(acc[mt][nt][1]),
                      "+f"(acc[mt][nt][2]), "+f"(acc[mt][nt][3])
                    : "r"(af[mt][0]), "r"(af[mt][1]), "r"(af[mt][2]), "r"(af[mt][3]),
                      "r"(bf[nt][0]), "r"(bf[nt][1]));
            }

        if (it + 2 < NIT) prefetch(it + 2, pf);
        buf = (buf + 1 == STG) ? 0 : buf + 1;
        pf  = (pf  + 1 == STG) ? 0 : pf + 1;
    }

#pragma unroll
    for (int mt = 0; mt < 4; mt++) {
        int row = m0 + wm * 64 + mt * 16 + (lane >> 2);
#pragma unroll
        for (int nt = 0; nt < 4; nt++) {
            int col = n0 + wn * 32 + nt * 8 + (lane & 3) * 2;
            float b0v = bias ? bias[col]     : 0.f;
            float b1v = bias ? bias[col + 1] : 0.f;
            float a0 = maybe_sig(acc[mt][nt][0] + b0v, col, sigmode);
            float a1 = maybe_sig(acc[mt][nt][1] + b1v, col + 1, sigmode);
            float a2 = maybe_sig(acc[mt][nt][2] + b0v, col, sigmode);
            float a3 = maybe_sig(acc[mt][nt][3] + b1v, col + 1, sigmode);
            if constexpr (sizeof(OutT) == 2) {
                *reinterpret_cast<__half2*>(&C[(size_t)row * ldc + col]) =
                    __floats2half2_rn(a0, a1);
                *reinterpret_cast<__half2*>(&C[(size_t)(row + 8) * ldc + col]) =
                    __floats2half2_rn(a2, a3);
            } else {
                *reinterpret_cast<float2*>(&C[(size_t)row * ldc + col]) = make_float2(a0, a1);
                *reinterpret_cast<float2*>(&C[(size_t)(row + 8) * ldc + col]) = make_float2(a2, a3);
            }
        }
    }
}

// ---------------------------------------------------------------------------
// Recurrence — chunked parallel scan (NCH=8). Proj now carries PRE-SIGMOIDED
// beta/gamma/p3; scan passes do no sigmoids.
// ---------------------------------------------------------------------------
#define NBUF 4

#define STAGE_BODY(T_, BUF_)                                                          \
    do {                                                                              \
        const int m_ = (T_) * BB + b;                                                 \
        {                                                                             \
            const int seg_ = d >> 4;                                                  \
            const int j_ = (d & 15) * 4;                                              \
            const float* src_ = proj + (size_t)m_ * LDP + seg_ * 512 + h * HDd + j_;  \
            unsigned dst_ = (unsigned)__cvta_generic_to_shared(&sstage[BUF_][seg_][j_]); \
            asm volatile("cp.async.ca.shared.global [%0], [%1], 16;\n" :: "r"(dst_), "l"(src_)); \
        }                                                                             \
        if (d < 16) {                                                                 \
            const float* src_ = proj + (size_t)m_ * LDP + 4 * 512 + h * HDd + d * 4;  \
            unsigned dst_ = (unsigned)__cvta_generic_to_shared(&sstage[BUF_][4][d * 4]); \
            asm volatile("cp.async.ca.shared.global [%0], [%1], 16;\n" :: "r"(dst_), "l"(src_)); \
        } else if (d < 19) {                                                          \
            const int j_ = d - 16;                                                    \
            const float* src_ = proj + (size_t)m_ * LDP + WROWS + j_ * 32 + h * ETA;  \
            unsigned dst_ = (unsigned)__cvta_generic_to_shared(&sp[BUF_][j_][0]);     \
            asm volatile("cp.async.ca.shared.global [%0], [%1], 16;\n" :: "r"(dst_), "l"(src_)); \
        } else if (d == 19) {                                                         \
            const int* src_ = term + m_;                                              \
            unsigned dst_ = (unsigned)__cvta_generic_to_shared(&sterm[BUF_]);         \
            asm volatile("cp.async.ca.shared.global [%0], [%1], 4;\n" :: "r"(dst_), "l"(src_)); \
        }                                                                             \
        asm volatile("cp.async.commit_group;\n");                                     \
    } while (0)

#define STAGE_BODY_NOQ(T_, BUF_)                                                      \
    do {                                                                              \
        const int m_ = (T_) * BB + b;                                                 \
        {                                                                             \
            const int seg_ = 1 + (d >> 4);                                            \
            const int j_ = (d & 15) * 4;                                              \
            const float* src_ = proj + (size_t)m_ * LDP + seg_ * 512 + h * HDd + j_;  \
            unsigned dst_ = (unsigned)__cvta_generic_to_shared(&sstage[BUF_][seg_][j_]); \
            asm volatile("cp.async.ca.shared.global [%0], [%1], 16;\n" :: "r"(dst_), "l"(src_)); \
        }                                                                             \
        if (d < 3) {                                                                  \
            const float* src_ = proj + (size_t)m_ * LDP + WROWS + d * 32 + h * ETA;   \
            unsigned dst_ = (unsigned)__cvta_generic_to_shared(&sp[BUF_][d][0]);      \
            asm volatile("cp.async.ca.shared.global [%0], [%1], 16;\n" :: "r"(dst_), "l"(src_)); \
        } else if (d == 3) {                                                          \
            const int* src_ = term + m_;                                              \
            unsigned dst_ = (unsigned)__cvta_generic_to_shared(&sterm[BUF_]);         \
            asm volatile("cp.async.ca.shared.global [%0], [%1], 4;\n" :: "r"(dst_), "l"(src_)); \
        }                                                                             \
        asm volatile("cp.async.commit_group;\n");                                     \
    } while (0)

#define OSC_INIT(BASE_)                                                   \
    const float PI = 3.14159265358979323846f;                             \
    float cr0, cr1, cr2, cr3, sr0, sr1, sr2, sr3;                         \
    float cw0, cw1, cw2, cw3, sw0, sw1, sw2, sw3;                         \
    {                                                                     \
        float om0 = -PI;                                                  \
        float om1 = -PI + 2.f * PI / 3.f;                                 \
        float om2 = -PI + 4.f * PI / 3.f;                                 \
        float om3 = PI;                                                   \
        float a;                                                          \
        a = (BASE_) * om0; cr0 = cosf(a); sr0 = sinf(a);                  \
        a = (BASE_) * om1; cr1 = cosf(a); sr1 = sinf(a);                  \
        a = (BASE_) * om2; cr2 = cosf(a); sr2 = sinf(a);                  \
        a = (BASE_) * om3; cr3 = cosf(a); sr3 = sinf(a);                  \
        cw0 = cosf(om0); sw0 = sinf(om0);                                 \
        cw1 = cosf(om1); sw1 = sinf(om1);                                 \
        cw2 = cosf(om2); sw2 = sinf(om2);                                 \
        cw3 = cosf(om3); sw3 = sinf(om3);                                 \
    }

#define OSC_STEP()                                                        \
    do { float c2_, s2_;                                                  \
        c2_ = cr0 * cw0 - sr0 * sw0; s2_ = sr0 * cw0 + cr0 * sw0; cr0 = c2_; sr0 = s2_; \
        c2_ = cr1 * cw1 - sr1 * sw1; s2_ = sr1 * cw1 + cr1 * sw1; cr1 = c2_; sr1 = s2_; \
        c2_ = cr2 * cw2 - sr2 * sw2; s2_ = sr2 * cw2 + cr2 * sw2; cr2 = c2_; sr2 = s2_; \
        c2_ = cr3 * cw3 - sr3 * sw3; s2_ = sr3 * cw3 + cr3 * sw3; cr3 = c2_; sr3 = s2_; \
    } while (0)

// Pass 1: chunk-local scan from zero state (no q; b/g/p3 pre-sigmoided).
__global__ __launch_bounds__(64) void scan_local(
    const float* __restrict__ proj, const int* __restrict__ term,
    const float* __restrict__ tick, float* __restrict__ scan)
{
    const int bh = blockIdx.x;
    const int c  = blockIdx.y;
    const int b = bh >> 3;
    const int h = bh & 7;
    const int d = threadIdx.x;
    const int t0 = c * TCH;

    __shared__ __align__(16) float sstage[NBUF][5][64];
    __shared__ __align__(16) float sp[NBUF][3][4];
    __shared__ int sterm[NBUF];

    float ks[4][4] = {}, ss[4] = {}, vs[4] = {};
    float Dk[4] = {1.f, 1.f, 1.f, 1.f}, Dv = 1.f;

    const float tk = tick[b];
    OSC_INIT((float)t0 + 1.f + tk);

    STAGE_BODY_NOQ(t0 + 0, 0);
    STAGE_BODY_NOQ(t0 + 1, 1);
    STAGE_BODY_NOQ(t0 + 2, 2);
    asm volatile("cp.async.wait_group 2;\n");
    __syncthreads();

    for (int tt = 0; tt < TCH; tt++) {
        const int buf = tt & (NBUF - 1);

        const float kd = sstage[buf][1][d];
        const float vv = sstage[buf][2][d];
        const float bd = sstage[buf][3][d];   // pre-sigmoided
        const float gd = sstage[buf][4][d];   // pre-sigmoided
        const float tf = 1.f - (float)sterm[buf];

#pragma unroll
        for (int e = 0; e < 4; e++) {
            const float psi = fmaxf(kd * sp[buf][0][e], 0.f);
            const float gf  = gd * sp[buf][2][e];   // p3 pre-sigmoided
            const float gk  = psi * gf;
            const float dg  = (1.f - gf) * tf;
            ss[e] = dg * ss[e] + gk;
            ks[e][0] = dg * ks[e][0] + gk * cr0;
            ks[e][1] = dg * ks[e][1] + gk * cr1;
            ks[e][2] = dg * ks[e][2] + gk * cr2;
            ks[e][3] = dg * ks[e][3] + gk * cr3;
            Dk[e] *= dg;
        }
        const float bv = vv * bd;
        const float om = (1.f - bd) * tf;
        vs[0] = om * vs[0] + bv * cr0;
        vs[1] = om * vs[1] + bv * cr1;
        vs[2] = om * vs[2] + bv * cr2;
        vs[3] = om * vs[3] + bv * cr3;
        Dv *= om;

        if (tt + 3 < TCH) {
            STAGE_BODY_NOQ(t0 + tt + 3, (tt + 3) & (NBUF - 1));
            asm volatile("cp.async.wait_group 2;\n");
        } else if (tt + 2 < TCH) {
            asm volatile("cp.async.wait_group 1;\n");
        } else {
            asm volatile("cp.async.wait_group 0;\n");
        }
        __syncthreads();
        OSC_STEP();
    }

    float* out = scan + (((size_t)c * 256 + bh) * 29) * 64;
#pragma unroll
    for (int e = 0; e < 4; e++)
#pragma unroll
        for (int r = 0; r < 4; r++)
            out[(e * 4 + r) * 64 + d] = ks[e][r];
#pragma unroll
    for (int e = 0; e < 4; e++) out[(16 + e) * 64 + d] = ss[e];
#pragma unroll
    for (int r = 0; r < 4; r++) out[(20 + r) * 64 + d] = vs[r];
#pragma unroll
    for (int e = 0; e < 4; e++) out[(24 + e) * 64 + d] = Dk[e];
    out[28 * 64 + d] = Dv;
}

// Pass 2: sequential combine; writes each chunk's true initial state.
__global__ __launch_bounds__(64) void scan_combine(
    const float* __restrict__ scan,
    const float* __restrict__ tkp, const float* __restrict__ tvp,
    const float* __restrict__ sprev, float* __restrict__ init)
{
    const int bh = blockIdx.x;
    const int b = bh >> 3;
    const int h = bh & 7;
    const int d = threadIdx.x;

    float ks[4][4], ss[4], vs[4];
#pragma unroll
    for (int e = 0; e < 4; e++) {
#pragma unroll
        for (int r = 0; r < 4; r++)
            ks[e][r] = tkp[((size_t)(b * RR + r) * HH + h) * FEAT + e * 64 + d];
        ss[e] = sprev[((size_t)(b * HH + h)) * FEAT + e * 64 + d];
    }
#pragma unroll
    for (int r = 0; r < 4; r++)
        vs[r] = tvp[((size_t)(b * RR + r) * HH + h) * HDd + d];

    for (int c = 0; c < NCH; c++) {
        float* ini = init + (((size_t)c * 256 + bh) * 24) * 64;
#pragma unroll
        for (int e = 0; e < 4; e++)
#pragma unroll
            for (int r = 0; r < 4; r++)
                ini[(e * 4 + r) * 64 + d] = ks[e][r];
#pragma unroll
        for (int e = 0; e < 4; e++) ini[(16 + e) * 64 + d] = ss[e];
#pragma unroll
        for (int r = 0; r < 4; r++) ini[(20 + r) * 64 + d] = vs[r];

        const float* sc = scan + (((size_t)c * 256 + bh) * 29) * 64;
        float Dk[4], Dv;
#pragma unroll
        for (int e = 0; e < 4; e++) Dk[e] = sc[(24 + e) * 64 + d];
        Dv = sc[28 * 64 + d];
#pragma unroll
        for (int e = 0; e < 4; e++) {
#pragma unroll
            for (int r = 0; r < 4; r++)
                ks[e][r] = sc[(e * 4 + r) * 64 + d] + Dk[e] * ks[e][r];
            ss[e] = sc[(16 + e) * 64 + d] + Dk[e] * ss[e];
        }
#pragma unroll
        for (int r = 0; r < 4; r++)
            vs[r] = sc[(20 + r) * 64 + d] + Dv * vs[r];
    }
}

// Pass 3: per-chunk full recurrence with true initial state; emits attn.
__global__ __launch_bounds__(64) void scan_apply(
    const float* __restrict__ proj, const int* __restrict__ term,
    const float* __restrict__ tick, const float* __restrict__ init,
    __half* __restrict__ attn)
{
    const int bh = blockIdx.x;
    const int c  = blockIdx.y;
    const int b = bh >> 3;
    const int h = bh & 7;
    const int d = threadIdx.x;
    const int t0 = c * TCH;

    __shared__ __align__(16) float sstage[NBUF][5][64];
    __shared__ __align__(16) float sp[NBUF][3][4];
    __shared__ int sterm[NBUF];
    __shared__ float red[2][5][2];

    float ks[4][4], ss[4], vs[4];
    const float* ini = init + (((size_t)c * 256 + bh) * 24) * 64;
#pragma unroll
    for (int e = 0; e < 4; e++)
#pragma unroll
        for (int r = 0; r < 4; r++)
            ks[e][r] = ini[(e * 4 + r) * 64 + d];
#pragma unroll
    for (int e = 0; e < 4; e++) ss[e] = ini[(16 + e) * 64 + d];
#pragma unroll
    for (int r = 0; r < 4; r++) vs[r] = ini[(20 + r) * 64 + d];

    const float tk = tick[b];
    OSC_INIT((float)t0 + 1.f + tk);

    STAGE_BODY(t0 + 0, 0);
    STAGE_BODY(t0 + 1, 1);
    STAGE_BODY(t0 + 2, 2);
    asm volatile("cp.async.wait_group 2;\n");
    __syncthreads();

    const int warp = d >> 5;

    for (int tt = 0; tt < TCH; tt++) {
        const int buf = tt & (NBUF - 1);

        const float qd = sstage[buf][0][d];
        const float kd = sstage[buf][1][d];
        const float vv = sstage[buf][2][d];
        const float bd = sstage[buf][3][d];   // pre-sigmoided
        const float gd = sstage[buf][4][d];   // pre-sigmoided
        const float tf = 1.f - (float)sterm[buf];

        float v0 = 0.f, v1 = 0.f, v2 = 0.f, v3 = 0.f, v4 = 0.f;
#pragma unroll
        for (int e = 0; e < 4; e++) {
            const float phi = fmaxf(qd * sp[buf][1][e], 0.f);
            const float psi = fmaxf(kd * sp[buf][0][e], 0.f);
            const float gf  = gd * sp[buf][2][e];   // p3 pre-sigmoided
            const float gk  = psi * gf;
            const float dg  = (1.f - gf) * tf;

            ss[e] = dg * ss[e] + gk;
            v4 += ss[e] * phi;

            ks[e][0] = dg * ks[e][0] + gk * cr0;  v0 += ks[e][0] * phi;
            ks[e][1] = dg * ks[e][1] + gk * cr1;  v1 += ks[e][1] * phi;
            ks[e][2] = dg * ks[e][2] + gk * cr2;  v2 += ks[e][2] * phi;
            ks[e][3] = dg * ks[e][3] + gk * cr3;  v3 += ks[e][3] * phi;
        }

        const float bv = vv * bd;
        const float om = (1.f - bd) * tf;
        vs[0] = om * vs[0] + bv * cr0;
        vs[1] = om * vs[1] + bv * cr1;
        vs[2] = om * vs[2] + bv * cr2;
        vs[3] = om * vs[3] + bv * cr3;

#pragma unroll
        for (int o = 16; o > 0; o >>= 1) {
            v0 += __shfl_xor_sync(0xffffffffu, v0, o);
            v1 += __shfl_xor_sync(0xffffffffu, v1, o);
            v2 += __shfl_xor_sync(0xffffffffu, v2, o);
            v3 += __shfl_xor_sync(0xffffffffu, v3, o);
            v4 += __shfl_xor_sync(0xffffffffu, v4, o);
        }
        const int pb = tt & 1;
        if ((d & 31) == 0) {
            red[pb][0][warp] = v0;
            red[pb][1][warp] = v1;
            red[pb][2][warp] = v2;
            red[pb][3][warp] = v3;
            red[pb][4][warp] = v4;
        }

        if (tt + 3 < TCH) {
            STAGE_BODY(t0 + tt + 3, (tt + 3) & (NBUF - 1));
            asm volatile("cp.async.wait_group 2;\n");
        } else if (tt + 2 < TCH) {
            asm volatile("cp.async.wait_group 1;\n");
        } else {
            asm volatile("cp.async.wait_group 0;\n");
        }
        __syncthreads();

        const float kdq0 = red[pb][0][0] + red[pb][0][1];
        const float kdq1 = red[pb][1][0] + red[pb][1][1];
        const float kdq2 = red[pb][2][0] + red[pb][2][1];
        const float kdq3 = red[pb][3][0] + red[pb][3][1];
        const float norm = red[pb][4][0] + red[pb][4][1];

        const float kv = vs[0] * kdq0 + vs[1] * kdq1 + vs[2] * kdq2 + vs[3] * kdq3;
        const int m = (t0 + tt) * BB + b;
        attn[(size_t)m * DD + h * HDd + d] = __float2half_rn(kv / (8.f * norm + 1e-6f));

        OSC_STEP();
    }
}

// ---------------------------------------------------------------------------
extern "C" void kernel_launch(void* const* d_in, const int* in_sizes, int n_in,
                              void* d_out, int out_size)
{
    const float* inputs = (const float*)d_in[0];
    const int*   term   = (const int*)d_in[1];
    const float* tkp    = (const float*)d_in[2];
    const float* tvp    = (const float*)d_in[3];
    const float* sprev  = (const float*)d_in[4];
    const float* tick   = (const float*)d_in[5];
    const float* Wq     = (const float*)d_in[6];
    const float* Wk     = (const float*)d_in[7];
    const float* Wv     = (const float*)d_in[8];
    const float* Wb     = (const float*)d_in[9];
    const float* Wg     = (const float*)d_in[10];
    const float* Wp1    = (const float*)d_in[11];
    const float* Wp2    = (const float*)d_in[12];
    const float* Wp3    = (const float*)d_in[13];
    const float* Wo     = (const float*)d_in[14];
    const float* bo     = (const float*)d_in[15];

    void* p;
    cudaGetSymbolAddress(&p, g_x);    __half* x    = (__half*)p;
    cudaGetSymbolAddress(&p, g_w5);   __half* w5   = (__half*)p;
    cudaGetSymbolAddress(&p, g_wo);   __half* wo   = (__half*)p;
    cudaGetSymbolAddress(&p, g_proj); float*  proj = (float*)p;
    cudaGetSymbolAddress(&p, g_attn); __half* attn = (__half*)p;
    cudaGetSymbolAddress(&p, g_scan); float*  scan = (float*)p;
    cudaGetSymbolAddress(&p, g_init); float*  init = (float*)p;

    // Prologue conversions
    cvt1_kernel<<<(MM * DD + 255) / 256, 256>>>(x, inputs, MM * DD);
    cvtw_kernel<<<(NW_TOTAL + 255) / 256, 256>>>(w5, wo, Wq, Wk, Wv, Wb, Wg,
                                                 Wp1, Wp2, Wp3, Wo);

    // 1) Fused projection with sigmoid epilogue on b/g/p3 columns
    {
        dim3 grid(LDP / GBN, MM / GBM);   // (21, 64)
        mma_gemm<float><<<grid, 256>>>(x, w5, proj, MM, LDP, DD, LDP, nullptr, 1);
    }
    // 2) Recurrence as 3-pass parallel scan (8 chunks of 32 steps)
    {
        dim3 g1(BB * HH, NCH);
        scan_local<<<g1, 64>>>(proj, term, tick, scan);
        scan_combine<<<BB * HH, 64>>>(scan, tkp, tvp, sprev, init);
        scan_apply<<<g1, 64>>>(proj, term, tick, init, attn);
    }
    // 3) Output projection: out = attn @ Wo^T + bo
    {
        dim3 grid(DD / GBN, MM / GBM);    // (4, 64)
        mma_gemm<float><<<grid, 256>>>(attn, wo, (float*)d_out, MM, DD, DD, DD, bo, 0);
    }
}